// round 12
// baseline (speedup 1.0000x reference)
#include <cuda_runtime.h>
#include <cuda_bf16.h>
#include <math.h>
#include <stdint.h>

// ---------------------------------------------------------------------------
// Problem constants
// ---------------------------------------------------------------------------
#define B_SZ 4096
#define K_SZ 64
#define D_SZ 8
#define F_SZ 2048
#define N_SZ 1024
#define NPAIR (K_SZ * (K_SZ + 1) / 2)
#define NTILE 272                 // 4x2 pair tiles covering lower triangle

#define OUT_CONCEPT_OFF (B_SZ)
#define OUT_COND_OFF (B_SZ + B_SZ * K_SZ)

// GEMM tiling: block 128x128, BK=32 (16 bf16x2 words), 2-stage cp.async pipe
// 128 threads (4 warps, 2m x 2n, warp tile 64x64), 2 CTAs/SM
#define GITERS (F_SZ / 32)        // 64
#define ASTRIDE 20
#define BSTRIDE 136
#define A_PLANE_W (128 * ASTRIDE)
#define B_PLANE_W (16 * BSTRIDE)
#define STAGE_W (2 * A_PLANE_W + 2 * B_PLANE_W)
#define SMEM_BYTES (2 * STAGE_W * 4)             // 75776 B -> 2 CTAs/SM

// ---------------------------------------------------------------------------
// Scratch (__device__ globals; no allocation)
// ---------------------------------------------------------------------------
__device__ __align__(256) float g_theta[(size_t)B_SZ * N_SZ];

// pre-split bf16 operands, packed as bf16x2 words
__device__ uint32_t g_AhiW[(size_t)B_SZ * (F_SZ / 2)];
__device__ uint32_t g_AloW[(size_t)B_SZ * (F_SZ / 2)];
__device__ uint32_t g_BhiW[(size_t)(F_SZ / 2) * N_SZ];
__device__ uint32_t g_BloW[(size_t)(F_SZ / 2) * N_SZ];

// ---------------------------------------------------------------------------
// math helpers
// ---------------------------------------------------------------------------
__device__ __forceinline__ float ex2f(float x) {
    float r; asm("ex2.approx.ftz.f32 %0, %1;" : "=f"(r) : "f"(x)); return r;
}
__device__ __forceinline__ float lg2f(float x) {
    float r; asm("lg2.approx.ftz.f32 %0, %1;" : "=f"(r) : "f"(x)); return r;
}
#define C_L2E   1.4426950408889634f
#define C_LN2   0.6931471805599453f

__device__ __forceinline__ float softplus_f(float x) {
    float u = ex2f(-C_L2E * fabsf(x));
    return fmaxf(x, 0.0f) + C_LN2 * lg2f(1.0f + u);
}
__device__ __forceinline__ float sigmoid_f(float x) {
    return 1.0f / (1.0f + ex2f(-C_L2E * x));
}

__device__ __forceinline__ void mma_bf16(float* c, const uint32_t* a, const uint32_t* b) {
    asm volatile(
        "mma.sync.aligned.m16n8k16.row.col.f32.bf16.bf16.f32 "
        "{%0,%1,%2,%3}, {%4,%5,%6,%7}, {%8,%9}, {%0,%1,%2,%3};"
        : "+f"(c[0]), "+f"(c[1]), "+f"(c[2]), "+f"(c[3])
        : "r"(a[0]), "r"(a[1]), "r"(a[2]), "r"(a[3]), "r"(b[0]), "r"(b[1]));
}

// ldmatrix x4 (portable sm_75+)
__device__ __forceinline__ void ldsm4(uint32_t* r, uint32_t saddr) {
    asm volatile("ldmatrix.sync.aligned.m8n8.x4.shared.b16 {%0,%1,%2,%3}, [%4];"
                 : "=r"(r[0]), "=r"(r[1]), "=r"(r[2]), "=r"(r[3]) : "r"(saddr));
}

// cp.async (portable sm_80+)
__device__ __forceinline__ void cp16(uint32_t saddr, const void* gptr) {
    asm volatile("cp.async.cg.shared.global [%0], [%1], 16;"
                 :: "r"(saddr), "l"((unsigned long long)__cvta_generic_to_global(gptr))
                 : "memory");
}
__device__ __forceinline__ void cp_commit() {
    asm volatile("cp.async.commit_group;" ::: "memory");
}
template <int N>
__device__ __forceinline__ void cp_wait() {
    asm volatile("cp.async.wait_group %0;" :: "n"(N) : "memory");
}

__device__ __forceinline__ uint32_t pack_hi(float x, float y) {
    __nv_bfloat162 v = __halves2bfloat162(__float2bfloat16(x), __float2bfloat16(y));
    return *(uint32_t*)&v;
}
__device__ __forceinline__ uint32_t pack_lo(float x, float y) {
    __nv_bfloat16 hx = __float2bfloat16(x);
    __nv_bfloat16 hy = __float2bfloat16(y);
    __nv_bfloat162 v = __halves2bfloat162(__float2bfloat16(x - __bfloat162float(hx)),
                                          __float2bfloat16(y - __bfloat162float(hy)));
    return *(uint32_t*)&v;
}

// ---------------------------------------------------------------------------
// Convert A: fp32 [4096,2048] -> packed bf16x2 hi/lo word arrays
// ---------------------------------------------------------------------------
__global__ __launch_bounds__(256)
void convert_A(const float* __restrict__ A)
{
    int gid = blockIdx.x * 256 + threadIdx.x;
    float4 v = *(const float4*)(A + (size_t)gid * 4);
    uint2 hi = make_uint2(pack_hi(v.x, v.y), pack_hi(v.z, v.w));
    uint2 lo = make_uint2(pack_lo(v.x, v.y), pack_lo(v.z, v.w));
    *(uint2*)(g_AhiW + (size_t)gid * 2) = hi;
    *(uint2*)(g_AloW + (size_t)gid * 2) = lo;
}

// ---------------------------------------------------------------------------
// Convert B: Wp[k][f][d] (n = k*16+d) -> word(fw, n) arrays
// ---------------------------------------------------------------------------
__global__ __launch_bounds__(256)
void convert_B(const float* __restrict__ Wp)
{
    int gid = blockIdx.x * 256 + threadIdx.x;
    int fw = gid >> 10;
    int n  = gid & 1023;
    int k = n >> 4, d = n & 15;
    const float* base = Wp + (size_t)k * (F_SZ * 16) + d;
    float x = base[(size_t)(2 * fw) * 16];
    float y = base[(size_t)(2 * fw + 1) * 16];
    g_BhiW[gid] = pack_hi(x, y);
    g_BloW[gid] = pack_lo(x, y);
}

// ---------------------------------------------------------------------------
// bf16 3-pass tensor-core GEMM.
// 128 threads, 4 warps (2m x 2n), warp tile 64x64 (mt=4, nt=8).
// A fragments via ldmatrix.x4; cp.async 2-stage pipeline; 2 CTAs/SM.
// Accumulation order per output element identical to R11 (bit-exact).
// ---------------------------------------------------------------------------
#define AS_IDX(s,p,m,kw) ((s) * STAGE_W + (p) * A_PLANE_W + (m) * ASTRIDE + (kw))
#define BS_IDX(s,p,kw,n) ((s) * STAGE_W + 2 * A_PLANE_W + (p) * B_PLANE_W + (kw) * BSTRIDE + (n))

__global__ __launch_bounds__(128, 2)
void gemm_bf16()
{
    extern __shared__ uint32_t sm[];
    const uint32_t smb = (uint32_t)__cvta_generic_to_shared(sm);

    const int tid  = threadIdx.x;
    const int lane = tid & 31;
    const int warp = tid >> 5;          // 0..3
    const int wm = warp & 1;            // m half
    const int wn = warp >> 1;           // n half
    const int bx = blockIdx.x;          // 0..7
    const int by = blockIdx.y;          // 0..31

    // ---- loaders (128 threads) ----
    // A: thread t loads row t (16 kwords = 4 cp16 per plane)
    const uint32_t* ApH = g_AhiW + (size_t)(by * 128 + tid) * (F_SZ / 2);
    const uint32_t* ApL = g_AloW + (size_t)(by * 128 + tid) * (F_SZ / 2);
    // B: thread t loads row fw = t>>3, n chunk (t&7)*16 (4 cp16 per plane)
    const int bfw = tid >> 3;           // 0..15
    const int bnc = (tid & 7) * 16;     // 0..112
    const uint32_t* BpH = g_BhiW + bx * 128 + bnc;
    const uint32_t* BpL = g_BloW + bx * 128 + bnc;

    const uint32_t sAh = smb + 4 * AS_IDX(0, 0, tid, 0);
    const uint32_t sAl = smb + 4 * AS_IDX(0, 1, tid, 0);
    const uint32_t sBh = smb + 4 * BS_IDX(0, 0, bfw, bnc);
    const uint32_t sBl = smb + 4 * BS_IDX(0, 1, bfw, bnc);

    // ldmatrix source address components (per-lane)
    const int lm   = lane >> 3;                    // matrix 0..3
    const int lrow = ((lm & 1) << 3) + (lane & 7); // row within 16
    const int lkw  = (lm >> 1) << 2;               // kword 0 or 4
    const uint32_t aoff = smb + 4 * ((wm * 64 + lrow) * ASTRIDE + lkw);

    float acc[4][8][4];
#pragma unroll
    for (int i = 0; i < 4; i++)
#pragma unroll
        for (int j = 0; j < 8; j++)
#pragma unroll
            for (int r = 0; r < 4; r++) acc[i][j][r] = 0.0f;

#define ISSUE(it, s) do {                                                     \
        const int kb_ = (it) * 16;                                            \
        const uint32_t so_ = (s) * (STAGE_W * 4);                             \
        _Pragma("unroll")                                                     \
        for (int c = 0; c < 4; ++c) {                                         \
            cp16(sAh + so_ + c * 16, ApH + kb_ + c * 4);                      \
            cp16(sAl + so_ + c * 16, ApL + kb_ + c * 4);                      \
        }                                                                     \
        const size_t gb_ = (size_t)(kb_ + bfw) * N_SZ;                        \
        _Pragma("unroll")                                                     \
        for (int c = 0; c < 4; ++c) {                                         \
            cp16(sBh + so_ + c * 16, BpH + gb_ + c * 4);                      \
            cp16(sBl + so_ + c * 16, BpL + gb_ + c * 4);                      \
        }                                                                     \
        cp_commit();                                                          \
    } while (0)

    ISSUE(0, 0);
    ISSUE(1, 1);

    const int bq = lane & 3;
    const int bc = lane >> 2;

    for (int it = 0; it < GITERS; ++it) {
        const int s = it & 1;

        if (it < GITERS - 1) cp_wait<1>(); else cp_wait<0>();
        __syncthreads();

#pragma unroll
        for (int ks = 0; ks < 2; ++ks) {
            const int kwb = ks * 8;
            uint32_t bh[8][2], bl[8][2];
#pragma unroll
            for (int nt = 0; nt < 8; ++nt) {
                const int n = wn * 64 + nt * 8 + bc;
                bh[nt][0] = sm[BS_IDX(s, 0, kwb + bq,     n)];
                bh[nt][1] = sm[BS_IDX(s, 0, kwb + bq + 4, n)];
                bl[nt][0] = sm[BS_IDX(s, 1, kwb + bq,     n)];
                bl[nt][1] = sm[BS_IDX(s, 1, kwb + bq + 4, n)];
            }
#pragma unroll
            for (int mt = 0; mt < 4; ++mt) {
                const uint32_t abase = aoff
                    + 4 * (s * STAGE_W + mt * 16 * ASTRIDE + kwb);
                uint32_t ah[4], al[4];
                ldsm4(ah, abase);
                ldsm4(al, abase + 4 * A_PLANE_W);
#pragma unroll
                for (int nt = 0; nt < 8; ++nt) {
                    mma_bf16(acc[mt][nt], ah, bh[nt]);
                    mma_bf16(acc[mt][nt], ah, bl[nt]);
                    mma_bf16(acc[mt][nt], al, bh[nt]);
                }
            }
        }

        __syncthreads();
        if (it + 2 < GITERS) ISSUE(it + 2, s);
    }
#undef ISSUE

    // epilogue
    const int mbase = by * 128 + wm * 64 + (lane >> 2);
    const int nbase = bx * 128 + wn * 64 + (lane & 3) * 2;
#pragma unroll
    for (int mt = 0; mt < 4; ++mt) {
#pragma unroll
        for (int nt = 0; nt < 8; ++nt) {
            const int m = mbase + mt * 16;
            const int n = nbase + nt * 8;
            float* p = g_theta + (size_t)m * N_SZ + n;
            p[0] = acc[mt][nt][0];
            p[1] = acc[mt][nt][1];
            p[(size_t)8 * N_SZ]     = acc[mt][nt][2];
            p[(size_t)8 * N_SZ + 1] = acc[mt][nt][3];
        }
    }
}

// ---------------------------------------------------------------------------
// Fused box + pair kernel (unchanged from R10 — at MUFU floor)
// ---------------------------------------------------------------------------
__global__ __launch_bounds__(256)
void fused_kernel(const float* __restrict__ bp, const float* __restrict__ Wprob,
                  const float* __restrict__ bprob, const float* __restrict__ Wbox,
                  const float* __restrict__ Wrel, const float* __restrict__ bbox,
                  const float* __restrict__ brel, float* __restrict__ out)
{
    const int b = blockIdx.x;
    const int tid = threadIdx.x;

    __shared__ __align__(16) float szt[D_SZ * K_SZ];   // [d][k]
    __shared__ __align__(16) float sZt[D_SZ * K_SZ];   // [d][k]
    __shared__ __align__(16) float srcp[K_SZ];
    __shared__ __align__(16) float sw[K_SZ * K_SZ];
    __shared__ __align__(16) float sc[K_SZ * K_SZ];
    __shared__ __align__(16) uint16_t stbl[NTILE];
    __shared__ float sbox[2];
    __shared__ float rr[8];

    if (tid >= 64) {
        for (int i = tid - 64; i < K_SZ * K_SZ; i += 192) sw[i] = Wrel[i];
    } else {
        // ---- box phase: one thread per k ----
        const int k = tid;
        const int lane = tid & 31;
        const float4* th4 = (const float4*)(g_theta + (size_t)b * N_SZ + k * 16);
        const float4* bp4 = (const float4*)(bp + k * 16);
        float4 t0 = th4[0], t1 = th4[1], t2 = th4[2], t3 = th4[3];
        float4 b0 = bp4[0], b1 = bp4[1], b2 = bp4[2], b3 = bp4[3];

        float z[8], Zb[8];
        float tz[8] = { t0.x + b0.x, t0.y + b0.y, t0.z + b0.z, t0.w + b0.w,
                        t1.x + b1.x, t1.y + b1.y, t1.z + b1.z, t1.w + b1.w };
        float tu[8] = { t2.x + b2.x, t2.y + b2.y, t2.z + b2.z, t2.w + b2.w,
                        t3.x + b3.x, t3.y + b3.y, t3.z + b3.z, t3.w + b3.w };
#pragma unroll
        for (int d = 0; d < 8; d++) {
            z[d]  = tz[d];
            Zb[d] = tz[d] + softplus_f(tu[d]);
        }

        // concept prob
        const float4* wp4 = (const float4*)(Wprob + k * 16);
        float4 w0 = wp4[0], w1 = wp4[1], w2 = wp4[2], w3 = wp4[3];
        const float wz[8] = { w0.x, w0.y, w0.z, w0.w, w1.x, w1.y, w1.z, w1.w };
        const float wZ[8] = { w2.x, w2.y, w2.z, w2.w, w3.x, w3.y, w3.z, w3.w };
        float logit = bprob[k];
#pragma unroll
        for (int d = 0; d < 8; d++)
            logit += z[d] * wz[d] + Zb[d] * wZ[d];
        float p = sigmoid_f(logit);
        out[OUT_CONCEPT_OFF + b * K_SZ + k] = p;

        // box volume, unscaled sides
        float P = 1.0f;
#pragma unroll
        for (int d = 0; d < 8; d++) {
            float x = 2.0f * (Zb[d] - z[d]);
            float u = ex2f(-C_L2E * x);
            float sp = x + C_LN2 * lg2f(1.0f + u);
            P *= fmaxf(sp, 2e-23f);
        }
        srcp[k] = 1.0f / P;

        // transposed stash
#pragma unroll
        for (int d = 0; d < 8; d++) { szt[d * K_SZ + k] = z[d]; sZt[d * K_SZ + k] = Zb[d]; }

        // box part of final logit
        const float4* wb4 = (const float4*)(Wbox + k * 16);
        float4 v0 = wb4[0], v1 = wb4[1], v2 = wb4[2], v3 = wb4[3];
        const float wbz[8] = { v0.x, v0.y, v0.z, v0.w, v1.x, v1.y, v1.z, v1.w };
        const float wbZ[8] = { v2.x, v2.y, v2.z, v2.w, v3.x, v3.y, v3.z, v3.w };
        float c = 0.0f;
#pragma unroll
        for (int d = 0; d < 8; d++)
            c += z[d] * wbz[d] + Zb[d] * wbZ[d];
        c *= p;
#pragma unroll
        for (int off = 16; off > 0; off >>= 1)
            c += __shfl_down_sync(0xffffffffu, c, off);
        if (lane == 0) sbox[tid >> 5] = c;

        // tile table
        if (k < 16) {
            const int ti = k;
            const int base = ti * ti + ti;
            for (int tj = 0; tj <= 2 * ti + 1; tj++)
                stbl[base + tj] = (uint16_t)((ti << 6) | tj);
        }
    }
    __syncthreads();

    // ---- pair phase: one 4x2 tile (8 pairs) per unit ----
    for (int u = tid; u < NTILE; u += 256) {
        const int v = stbl[u];
        const int i0 = (v >> 6) * 4;
        const int j0 = (v & 63) * 2;

        float P[8];
#pragma unroll
        for (int q = 0; q < 8; q++) P[q] = 1.0f;

#pragma unroll 1
        for (int d = 0; d < 8; d++) {
            const float* zr = szt + d * K_SZ;
            const float* Zr = sZt + d * K_SZ;
            float zi[4], Zi[4], zj[2], Zj[2];
#pragma unroll
            for (int ii = 0; ii < 4; ii++) { zi[ii] = zr[i0 + ii]; Zi[ii] = Zr[i0 + ii]; }
#pragma unroll
            for (int jj = 0; jj < 2; jj++) { zj[jj] = zr[j0 + jj]; Zj[jj] = Zr[j0 + jj]; }

#pragma unroll
            for (int ii = 0; ii < 4; ii++) {
#pragma unroll
                for (int jj = 0; jj < 2; jj++) {
                    float d1 = zi[ii] - zj[jj];
                    float d2 = Zi[ii] - Zj[jj];
                    float e1 = ex2f(-10.0f * C_L2E * fabsf(d1));
                    float e2 = ex2f(-10.0f * C_L2E * fabsf(d2));
                    float s  = fmaf(e1, e2, e1) + e2;
                    float t2 = lg2f(1.0f + s);
                    float gap = fminf(Zi[ii], Zj[jj]) - fmaxf(zi[ii], zj[jj]);
                    float x  = fmaf(-0.2f * C_LN2, t2, gap + gap);
                    float uu = ex2f(-C_L2E * fabsf(x));
                    float vv = lg2f(1.0f + uu);
                    float sp = fmaf(C_LN2, vv, fmaxf(x, 0.0f));
                    P[ii * 2 + jj] *= fmaxf(sp, 2e-23f);
                }
            }
        }

#pragma unroll
        for (int ii = 0; ii < 4; ii++) {
            const int i = i0 + ii;
#pragma unroll
            for (int jj = 0; jj < 2; jj++) {
                const int j = j0 + jj;
                if (j <= i) {
                    float Pv = P[ii * 2 + jj];
                    float cij = Pv * srcp[j];
                    cij = fminf(fmaxf(cij, 1e-6f), 1.0f - 1e-6f);
                    float cji = Pv * srcp[i];
                    cji = fminf(fmaxf(cji, 1e-6f), 1.0f - 1e-6f);
                    sc[i * K_SZ + j] = cij;
                    sc[j * K_SZ + i] = cji;
                }
            }
        }
    }
    __syncthreads();

    // coalesced cond writeout + flat_rel @ Wrel
    float acc = 0.0f;
    float4* condout = (float4*)(out + OUT_COND_OFF + (size_t)b * (K_SZ * K_SZ));
    for (int q = tid; q < (K_SZ * K_SZ) / 4; q += 256) {
        float4 v = *(const float4*)&sc[q * 4];
        float4 w = *(const float4*)&sw[q * 4];
        condout[q] = v;
        acc += v.x * w.x + v.y * w.y + v.z * w.z + v.w * w.w;
    }

#pragma unroll
    for (int off = 16; off > 0; off >>= 1)
        acc += __shfl_down_sync(0xffffffffu, acc, off);
    if ((tid & 31) == 0) rr[tid >> 5] = acc;
    __syncthreads();
    if (tid == 0) {
        float s = 0.0f;
#pragma unroll
        for (int w = 0; w < 8; w++) s += rr[w];
        float logit = sbox[0] + sbox[1] + bbox[0] + s + brel[0];
        out[b] = sigmoid_f(logit);
    }
}

// ---------------------------------------------------------------------------
extern "C" void kernel_launch(void* const* d_in, const int* in_sizes, int n_in,
                              void* d_out, int out_size)
{
    const float* features = (const float*)d_in[0];
    const float* Wp       = (const float*)d_in[1];
    const float* bp       = (const float*)d_in[2];
    const float* Wprob    = (const float*)d_in[3];
    const float* bprob    = (const float*)d_in[4];
    const float* Wbox     = (const float*)d_in[5];
    const float* bbox     = (const float*)d_in[6];
    const float* Wrel     = (const float*)d_in[7];
    const float* brel     = (const float*)d_in[8];
    float* out = (float*)d_out;

    cudaFuncSetAttribute(gemm_bf16, cudaFuncAttributeMaxDynamicSharedMemorySize, SMEM_BYTES);

    convert_A<<<(B_SZ * F_SZ / 4) / 256, 256>>>(features);
    convert_B<<<(F_SZ / 2) * N_SZ / 256, 256>>>(Wp);
    gemm_bf16<<<dim3(8, 32), 128, SMEM_BYTES>>>();
    fused_kernel<<<B_SZ, 256>>>(bp, Wprob, bprob, Wbox, Wrel, bbox, brel, out);
}

// round 13
// speedup vs baseline: 1.1592x; 1.1592x over previous
#include <cuda_runtime.h>
#include <cuda_bf16.h>
#include <math.h>
#include <stdint.h>

// ---------------------------------------------------------------------------
// Problem constants
// ---------------------------------------------------------------------------
#define B_SZ 4096
#define K_SZ 64
#define D_SZ 8
#define F_SZ 2048
#define N_SZ 1024
#define NPAIR (K_SZ * (K_SZ + 1) / 2)
#define NTILE 272                 // 4x2 pair tiles covering lower triangle

#define OUT_CONCEPT_OFF (B_SZ)
#define OUT_COND_OFF (B_SZ + B_SZ * K_SZ)

// GEMM tiling: block 128x128, BK=32 (16 bf16x2 words), 2-stage cp.async pipe
// 256 threads (8 warps, 2m x 4n, warp tile 64x32), 2 CTAs/SM  [R11 shape]
#define GITERS (F_SZ / 32)        // 64
#define ASTRIDE 20
#define BSTRIDE 136
#define A_PLANE_W (128 * ASTRIDE)
#define B_PLANE_W (16 * BSTRIDE)
#define STAGE_W (2 * A_PLANE_W + 2 * B_PLANE_W)
#define SMEM_BYTES (2 * STAGE_W * 4)             // 75776 B -> 2 CTAs/SM

// ---------------------------------------------------------------------------
// Scratch (__device__ globals; no allocation)
// ---------------------------------------------------------------------------
__device__ __align__(256) float g_theta[(size_t)B_SZ * N_SZ];

// pre-split bf16 operands, packed as bf16x2 words
__device__ uint32_t g_AhiW[(size_t)B_SZ * (F_SZ / 2)];
__device__ uint32_t g_AloW[(size_t)B_SZ * (F_SZ / 2)];
__device__ uint32_t g_BhiW[(size_t)(F_SZ / 2) * N_SZ];
__device__ uint32_t g_BloW[(size_t)(F_SZ / 2) * N_SZ];

// ---------------------------------------------------------------------------
// math helpers
// ---------------------------------------------------------------------------
__device__ __forceinline__ float ex2f(float x) {
    float r; asm("ex2.approx.ftz.f32 %0, %1;" : "=f"(r) : "f"(x)); return r;
}
__device__ __forceinline__ float lg2f(float x) {
    float r; asm("lg2.approx.ftz.f32 %0, %1;" : "=f"(r) : "f"(x)); return r;
}
#define C_L2E   1.4426950408889634f
#define C_LN2   0.6931471805599453f

__device__ __forceinline__ float softplus_f(float x) {
    float u = ex2f(-C_L2E * fabsf(x));
    return fmaxf(x, 0.0f) + C_LN2 * lg2f(1.0f + u);
}
__device__ __forceinline__ float sigmoid_f(float x) {
    return 1.0f / (1.0f + ex2f(-C_L2E * x));
}

__device__ __forceinline__ void mma_bf16(float* c, const uint32_t* a, const uint32_t* b) {
    asm volatile(
        "mma.sync.aligned.m16n8k16.row.col.f32.bf16.bf16.f32 "
        "{%0,%1,%2,%3}, {%4,%5,%6,%7}, {%8,%9}, {%0,%1,%2,%3};"
        : "+f"(c[0]), "+f"(c[1]), "+f"(c[2]), "+f"(c[3])
        : "r"(a[0]), "r"(a[1]), "r"(a[2]), "r"(a[3]), "r"(b[0]), "r"(b[1]));
}

// ldmatrix x4 (portable sm_75+)
__device__ __forceinline__ void ldsm4(uint32_t* r, uint32_t saddr) {
    asm volatile("ldmatrix.sync.aligned.m8n8.x4.shared.b16 {%0,%1,%2,%3}, [%4];"
                 : "=r"(r[0]), "=r"(r[1]), "=r"(r[2]), "=r"(r[3]) : "r"(saddr));
}

// cp.async (portable sm_80+)
__device__ __forceinline__ void cp16(uint32_t saddr, const void* gptr) {
    asm volatile("cp.async.cg.shared.global [%0], [%1], 16;"
                 :: "r"(saddr), "l"((unsigned long long)__cvta_generic_to_global(gptr))
                 : "memory");
}
__device__ __forceinline__ void cp_commit() {
    asm volatile("cp.async.commit_group;" ::: "memory");
}
template <int N>
__device__ __forceinline__ void cp_wait() {
    asm volatile("cp.async.wait_group %0;" :: "n"(N) : "memory");
}

__device__ __forceinline__ uint32_t pack_hi(float x, float y) {
    __nv_bfloat162 v = __halves2bfloat162(__float2bfloat16(x), __float2bfloat16(y));
    return *(uint32_t*)&v;
}
__device__ __forceinline__ uint32_t pack_lo(float x, float y) {
    __nv_bfloat16 hx = __float2bfloat16(x);
    __nv_bfloat16 hy = __float2bfloat16(y);
    __nv_bfloat162 v = __halves2bfloat162(__float2bfloat16(x - __bfloat162float(hx)),
                                          __float2bfloat16(y - __bfloat162float(hy)));
    return *(uint32_t*)&v;
}

// ---------------------------------------------------------------------------
// Merged convert kernel: blocks [0, 8192) do A, [8192, 12288) do B.
// ---------------------------------------------------------------------------
#define A_BLOCKS ((B_SZ * F_SZ / 4) / 256)        // 8192
#define B_BLOCKS (((F_SZ / 2) * N_SZ) / 256)      // 4096

__global__ __launch_bounds__(256)
void convert_AB(const float* __restrict__ A, const float* __restrict__ Wp)
{
    if (blockIdx.x < A_BLOCKS) {
        int gid = blockIdx.x * 256 + threadIdx.x;
        float4 v = *(const float4*)(A + (size_t)gid * 4);
        uint2 hi = make_uint2(pack_hi(v.x, v.y), pack_hi(v.z, v.w));
        uint2 lo = make_uint2(pack_lo(v.x, v.y), pack_lo(v.z, v.w));
        *(uint2*)(g_AhiW + (size_t)gid * 2) = hi;
        *(uint2*)(g_AloW + (size_t)gid * 2) = lo;
    } else {
        int gid = (blockIdx.x - A_BLOCKS) * 256 + threadIdx.x;
        int fw = gid >> 10;
        int n  = gid & 1023;
        int k = n >> 4, d = n & 15;
        const float* base = Wp + (size_t)k * (F_SZ * 16) + d;
        float x = base[(size_t)(2 * fw) * 16];
        float y = base[(size_t)(2 * fw + 1) * 16];
        g_BhiW[gid] = pack_hi(x, y);
        g_BloW[gid] = pack_lo(x, y);
    }
}

// ---------------------------------------------------------------------------
// bf16 3-pass tensor-core GEMM — R11 shape (256 thr, 8 warps 2m x 4n,
// warp tile 64x32, cp.async 2-stage, 2 CTAs/SM) + ldmatrix.x4 A fragments.
// Accumulation order per output element identical to R11 (bit-exact).
// ---------------------------------------------------------------------------
#define AS_IDX(s,p,m,kw) ((s) * STAGE_W + (p) * A_PLANE_W + (m) * ASTRIDE + (kw))
#define BS_IDX(s,p,kw,n) ((s) * STAGE_W + 2 * A_PLANE_W + (p) * B_PLANE_W + (kw) * BSTRIDE + (n))

__global__ __launch_bounds__(256, 2)
void gemm_bf16()
{
    extern __shared__ uint32_t sm[];
    const uint32_t smb = (uint32_t)__cvta_generic_to_shared(sm);

    const int tid  = threadIdx.x;
    const int lane = tid & 31;
    const int warp = tid >> 5;
    const int wm = warp & 1;
    const int wn = warp >> 1;
    const int bx = blockIdx.x;
    const int by = blockIdx.y;

    // global load mapping (R11)
    const int am  = tid >> 1;            // 0..127
    const int akw = (tid & 1) * 8;       // 0 or 8
    const uint32_t* ApH = g_AhiW + (size_t)(by * 128 + am) * (F_SZ / 2) + akw;
    const uint32_t* ApL = g_AloW + (size_t)(by * 128 + am) * (F_SZ / 2) + akw;
    const int bfw = tid >> 4;            // 0..15
    const int bnf = (tid & 15) * 8;      // 0..120
    const uint32_t* BpH = g_BhiW + (size_t)bfw * N_SZ + bx * 128 + bnf;
    const uint32_t* BpL = g_BloW + (size_t)bfw * N_SZ + bx * 128 + bnf;

    const uint32_t sAh = smb + 4 * AS_IDX(0, 0, am, akw);
    const uint32_t sAl = smb + 4 * AS_IDX(0, 1, am, akw);
    const uint32_t sBh = smb + 4 * BS_IDX(0, 0, bfw, bnf);
    const uint32_t sBl = smb + 4 * BS_IDX(0, 1, bfw, bnf);

    // ldmatrix per-lane source components (reproduces R11 fragment values)
    const int lm   = lane >> 3;                    // matrix 0..3
    const int lrow = ((lm & 1) << 3) + (lane & 7); // row within 16
    const int lkw  = (lm >> 1) << 2;               // kword 0 or 4

    float acc[4][4][4];
#pragma unroll
    for (int i = 0; i < 4; i++)
#pragma unroll
        for (int j = 0; j < 4; j++)
#pragma unroll
            for (int r = 0; r < 4; r++) acc[i][j][r] = 0.0f;

#define ISSUE(it, s) do {                                                     \
        const int kb_ = (it) * 16;                                            \
        const uint32_t so_ = (s) * (STAGE_W * 4);                             \
        cp16(sAh + so_,      ApH + kb_);                                      \
        cp16(sAh + so_ + 16, ApH + kb_ + 4);                                  \
        cp16(sAl + so_,      ApL + kb_);                                      \
        cp16(sAl + so_ + 16, ApL + kb_ + 4);                                  \
        const size_t gb_ = (size_t)kb_ * N_SZ;                                \
        cp16(sBh + so_,      BpH + gb_);                                      \
        cp16(sBh + so_ + 16, BpH + gb_ + 4);                                  \
        cp16(sBl + so_,      BpL + gb_);                                      \
        cp16(sBl + so_ + 16, BpL + gb_ + 4);                                  \
        cp_commit();                                                          \
    } while (0)

    ISSUE(0, 0);
    ISSUE(1, 1);

    const int bq = lane & 3;
    const int bc = lane >> 2;

    for (int it = 0; it < GITERS; ++it) {
        const int s = it & 1;

        if (it < GITERS - 1) cp_wait<1>(); else cp_wait<0>();
        __syncthreads();

#pragma unroll
        for (int ks = 0; ks < 2; ++ks) {
            const int kwb = ks * 8;
            uint32_t bh[4][2], bl[4][2];
#pragma unroll
            for (int nt = 0; nt < 4; ++nt) {
                const int n = wn * 32 + nt * 8 + bc;
                bh[nt][0] = sm[BS_IDX(s, 0, kwb + bq,     n)];
                bh[nt][1] = sm[BS_IDX(s, 0, kwb + bq + 4, n)];
                bl[nt][0] = sm[BS_IDX(s, 1, kwb + bq,     n)];
                bl[nt][1] = sm[BS_IDX(s, 1, kwb + bq + 4, n)];
            }
#pragma unroll
            for (int mt = 0; mt < 4; ++mt) {
                const uint32_t abase = smb
                    + 4 * AS_IDX(s, 0, wm * 64 + mt * 16 + lrow, kwb + lkw);
                uint32_t ah[4], al[4];
                ldsm4(ah, abase);
                ldsm4(al, abase + 4 * A_PLANE_W);
#pragma unroll
                for (int nt = 0; nt < 4; ++nt) {
                    mma_bf16(acc[mt][nt], ah, bh[nt]);
                    mma_bf16(acc[mt][nt], ah, bl[nt]);
                    mma_bf16(acc[mt][nt], al, bh[nt]);
                }
            }
        }

        __syncthreads();
        if (it + 2 < GITERS) ISSUE(it + 2, s);
    }
#undef ISSUE

    // epilogue
    const int mbase = by * 128 + wm * 64 + (lane >> 2);
    const int nbase = bx * 128 + wn * 32 + (lane & 3) * 2;
#pragma unroll
    for (int mt = 0; mt < 4; ++mt) {
#pragma unroll
        for (int nt = 0; nt < 4; ++nt) {
            const int m = mbase + mt * 16;
            const int n = nbase + nt * 8;
            float* p = g_theta + (size_t)m * N_SZ + n;
            p[0] = acc[mt][nt][0];
            p[1] = acc[mt][nt][1];
            p[(size_t)8 * N_SZ]     = acc[mt][nt][2];
            p[(size_t)8 * N_SZ + 1] = acc[mt][nt][3];
        }
    }
}

// ---------------------------------------------------------------------------
// Fused box + pair kernel (unchanged from R10 — at MUFU floor)
// ---------------------------------------------------------------------------
__global__ __launch_bounds__(256)
void fused_kernel(const float* __restrict__ bp, const float* __restrict__ Wprob,
                  const float* __restrict__ bprob, const float* __restrict__ Wbox,
                  const float* __restrict__ Wrel, const float* __restrict__ bbox,
                  const float* __restrict__ brel, float* __restrict__ out)
{
    const int b = blockIdx.x;
    const int tid = threadIdx.x;

    __shared__ __align__(16) float szt[D_SZ * K_SZ];   // [d][k]
    __shared__ __align__(16) float sZt[D_SZ * K_SZ];   // [d][k]
    __shared__ __align__(16) float srcp[K_SZ];
    __shared__ __align__(16) float sw[K_SZ * K_SZ];
    __shared__ __align__(16) float sc[K_SZ * K_SZ];
    __shared__ __align__(16) uint16_t stbl[NTILE];
    __shared__ float sbox[2];
    __shared__ float rr[8];

    if (tid >= 64) {
        for (int i = tid - 64; i < K_SZ * K_SZ; i += 192) sw[i] = Wrel[i];
    } else {
        // ---- box phase: one thread per k ----
        const int k = tid;
        const int lane = tid & 31;
        const float4* th4 = (const float4*)(g_theta + (size_t)b * N_SZ + k * 16);
        const float4* bp4 = (const float4*)(bp + k * 16);
        float4 t0 = th4[0], t1 = th4[1], t2 = th4[2], t3 = th4[3];
        float4 b0 = bp4[0], b1 = bp4[1], b2 = bp4[2], b3 = bp4[3];

        float z[8], Zb[8];
        float tz[8] = { t0.x + b0.x, t0.y + b0.y, t0.z + b0.z, t0.w + b0.w,
                        t1.x + b1.x, t1.y + b1.y, t1.z + b1.z, t1.w + b1.w };
        float tu[8] = { t2.x + b2.x, t2.y + b2.y, t2.z + b2.z, t2.w + b2.w,
                        t3.x + b3.x, t3.y + b3.y, t3.z + b3.z, t3.w + b3.w };
#pragma unroll
        for (int d = 0; d < 8; d++) {
            z[d]  = tz[d];
            Zb[d] = tz[d] + softplus_f(tu[d]);
        }

        // concept prob
        const float4* wp4 = (const float4*)(Wprob + k * 16);
        float4 w0 = wp4[0], w1 = wp4[1], w2 = wp4[2], w3 = wp4[3];
        const float wz[8] = { w0.x, w0.y, w0.z, w0.w, w1.x, w1.y, w1.z, w1.w };
        const float wZ[8] = { w2.x, w2.y, w2.z, w2.w, w3.x, w3.y, w3.z, w3.w };
        float logit = bprob[k];
#pragma unroll
        for (int d = 0; d < 8; d++)
            logit += z[d] * wz[d] + Zb[d] * wZ[d];
        float p = sigmoid_f(logit);
        out[OUT_CONCEPT_OFF + b * K_SZ + k] = p;

        // box volume, unscaled sides
        float P = 1.0f;
#pragma unroll
        for (int d = 0; d < 8; d++) {
            float x = 2.0f * (Zb[d] - z[d]);
            float u = ex2f(-C_L2E * x);
            float sp = x + C_LN2 * lg2f(1.0f + u);
            P *= fmaxf(sp, 2e-23f);
        }
        srcp[k] = 1.0f / P;

        // transposed stash
#pragma unroll
        for (int d = 0; d < 8; d++) { szt[d * K_SZ + k] = z[d]; sZt[d * K_SZ + k] = Zb[d]; }

        // box part of final logit
        const float4* wb4 = (const float4*)(Wbox + k * 16);
        float4 v0 = wb4[0], v1 = wb4[1], v2 = wb4[2], v3 = wb4[3];
        const float wbz[8] = { v0.x, v0.y, v0.z, v0.w, v1.x, v1.y, v1.z, v1.w };
        const float wbZ[8] = { v2.x, v2.y, v2.z, v2.w, v3.x, v3.y, v3.z, v3.w };
        float c = 0.0f;
#pragma unroll
        for (int d = 0; d < 8; d++)
            c += z[d] * wbz[d] + Zb[d] * wbZ[d];
        c *= p;
#pragma unroll
        for (int off = 16; off > 0; off >>= 1)
            c += __shfl_down_sync(0xffffffffu, c, off);
        if (lane == 0) sbox[tid >> 5] = c;

        // tile table
        if (k < 16) {
            const int ti = k;
            const int base = ti * ti + ti;
            for (int tj = 0; tj <= 2 * ti + 1; tj++)
                stbl[base + tj] = (uint16_t)((ti << 6) | tj);
        }
    }
    __syncthreads();

    // ---- pair phase: one 4x2 tile (8 pairs) per unit ----
    for (int u = tid; u < NTILE; u += 256) {
        const int v = stbl[u];
        const int i0 = (v >> 6) * 4;
        const int j0 = (v & 63) * 2;

        float P[8];
#pragma unroll
        for (int q = 0; q < 8; q++) P[q] = 1.0f;

#pragma unroll 1
        for (int d = 0; d < 8; d++) {
            const float* zr = szt + d * K_SZ;
            const float* Zr = sZt + d * K_SZ;
            float zi[4], Zi[4], zj[2], Zj[2];
#pragma unroll
            for (int ii = 0; ii < 4; ii++) { zi[ii] = zr[i0 + ii]; Zi[ii] = Zr[i0 + ii]; }
#pragma unroll
            for (int jj = 0; jj < 2; jj++) { zj[jj] = zr[j0 + jj]; Zj[jj] = Zr[j0 + jj]; }

#pragma unroll
            for (int ii = 0; ii < 4; ii++) {
#pragma unroll
                for (int jj = 0; jj < 2; jj++) {
                    float d1 = zi[ii] - zj[jj];
                    float d2 = Zi[ii] - Zj[jj];
                    float e1 = ex2f(-10.0f * C_L2E * fabsf(d1));
                    float e2 = ex2f(-10.0f * C_L2E * fabsf(d2));
                    float s  = fmaf(e1, e2, e1) + e2;
                    float t2 = lg2f(1.0f + s);
                    float gap = fminf(Zi[ii], Zj[jj]) - fmaxf(zi[ii], zj[jj]);
                    float x  = fmaf(-0.2f * C_LN2, t2, gap + gap);
                    float uu = ex2f(-C_L2E * fabsf(x));
                    float vv = lg2f(1.0f + uu);
                    float sp = fmaf(C_LN2, vv, fmaxf(x, 0.0f));
                    P[ii * 2 + jj] *= fmaxf(sp, 2e-23f);
                }
            }
        }

#pragma unroll
        for (int ii = 0; ii < 4; ii++) {
            const int i = i0 + ii;
#pragma unroll
            for (int jj = 0; jj < 2; jj++) {
                const int j = j0 + jj;
                if (j <= i) {
                    float Pv = P[ii * 2 + jj];
                    float cij = Pv * srcp[j];
                    cij = fminf(fmaxf(cij, 1e-6f), 1.0f - 1e-6f);
                    float cji = Pv * srcp[i];
                    cji = fminf(fmaxf(cji, 1e-6f), 1.0f - 1e-6f);
                    sc[i * K_SZ + j] = cij;
                    sc[j * K_SZ + i] = cji;
                }
            }
        }
    }
    __syncthreads();

    // coalesced cond writeout + flat_rel @ Wrel
    float acc = 0.0f;
    float4* condout = (float4*)(out + OUT_COND_OFF + (size_t)b * (K_SZ * K_SZ));
    for (int q = tid; q < (K_SZ * K_SZ) / 4; q += 256) {
        float4 v = *(const float4*)&sc[q * 4];
        float4 w = *(const float4*)&sw[q * 4];
        condout[q] = v;
        acc += v.x * w.x + v.y * w.y + v.z * w.z + v.w * w.w;
    }

#pragma unroll
    for (int off = 16; off > 0; off >>= 1)
        acc += __shfl_down_sync(0xffffffffu, acc, off);
    if ((tid & 31) == 0) rr[tid >> 5] = acc;
    __syncthreads();
    if (tid == 0) {
        float s = 0.0f;
#pragma unroll
        for (int w = 0; w < 8; w++) s += rr[w];
        float logit = sbox[0] + sbox[1] + bbox[0] + s + brel[0];
        out[b] = sigmoid_f(logit);
    }
}

// ---------------------------------------------------------------------------
extern "C" void kernel_launch(void* const* d_in, const int* in_sizes, int n_in,
                              void* d_out, int out_size)
{
    const float* features = (const float*)d_in[0];
    const float* Wp       = (const float*)d_in[1];
    const float* bp       = (const float*)d_in[2];
    const float* Wprob    = (const float*)d_in[3];
    const float* bprob    = (const float*)d_in[4];
    const float* Wbox     = (const float*)d_in[5];
    const float* bbox     = (const float*)d_in[6];
    const float* Wrel     = (const float*)d_in[7];
    const float* brel     = (const float*)d_in[8];
    float* out = (float*)d_out;

    cudaFuncSetAttribute(gemm_bf16, cudaFuncAttributeMaxDynamicSharedMemorySize, SMEM_BYTES);

    convert_AB<<<A_BLOCKS + B_BLOCKS, 256>>>(features, Wp);
    gemm_bf16<<<dim3(8, 32), 256, SMEM_BYTES>>>();
    fused_kernel<<<B_SZ, 256>>>(bp, Wprob, bprob, Wbox, Wrel, bbox, brel, out);
}